// round 17
// baseline (speedup 1.0000x reference)
#include <cuda_runtime.h>

// CountVectorizer == per-row bincount over vocab followed by counts @ W + b.
//   out[b, :] = bias + sum_t W[token_ids[b, t], :]   (embedding gather-sum)
//
// R15 calibration: byte-identical champion source measured 12.288 vs 11.296
// across sessions -> ~1 us run-to-run noise; all micro-shape variants
// (width/unroll5/cache-op/policy) are within noise of each other. Real
// effects only: float1 and two-wave (+3 us), unroll 2/10 (+1 us).
// This round changes the physics instead of the shape: SORT each row's ids
// ascending before gathering (sum is order-independent). All 1024 CTAs run
// as one lockstep wave, so at any instant every CTA gathers near the same
// vocab quantile (~2 MB hot window): the chip performs a coordinated
// sequential sweep of W -> DRAM goes from random 512B requests (3.4 TB/s
// measured) to one streaming 51 MB pass, and gathers hit a small hot L2
// region. Sort = 256-wide bitonic in smem (36 passes, ~1.5-2 us), paid once
// per row; gather stage mirrors the champion (float2, 50 tok/warp, unroll 5,
// .cg L1-bypass, raw-id IMAD.WIDE addressing).
// (Resubmission of R16 verbatim: that round died on the recurring broker
// infra flake - 5th occurrence - not the kernel.)

#define CV_BATCH  1024
#define CV_SEQ    200
#define CV_NSORT  256               // padded sort size (pow2)
#define CV_D      128               // d_model
#define CV_D2     (CV_D / 2)        // 64 float2 per full row

__global__ __launch_bounds__(256)
void count_vectorizer_kernel(const int* __restrict__ token_ids,
                             const float2* __restrict__ W2,
                             const float2* __restrict__ bias2,
                             float2* __restrict__ out2)
{
    __shared__ int    s_ids[CV_NSORT];
    __shared__ float2 s_acc[4][CV_D2];   // per-stream partials, 2 KB

    const int b   = blockIdx.x;          // one CTA per batch row
    const int tid = threadIdx.x;

    // Stage ids; pad with INT_MAX so sentinels sort to positions 200..255.
    s_ids[tid] = (tid < CV_SEQ) ? token_ids[b * CV_SEQ + tid] : 0x7FFFFFFF;
    __syncthreads();

    // Bitonic sort, 256 elements, 256 threads, ascending.
    for (int k = 2; k <= CV_NSORT; k <<= 1) {
        for (int j = k >> 1; j > 0; j >>= 1) {
            const int i   = tid;
            const int ixj = i ^ j;
            if (ixj > i) {
                const int a = s_ids[i];
                const int c = s_ids[ixj];
                if ((a > c) == ((i & k) == 0)) {
                    s_ids[i]   = c;
                    s_ids[ixj] = a;
                }
            }
            __syncthreads();
        }
    }
    // Real ids now occupy s_ids[0..199] in ascending order.

    const int lane = tid & 31;
    const int w    = tid >> 5;           // warp 0..7
    const int s    = w & 3;              // token stream 0..3
    const int h    = w >> 2;             // d-half
    const int dcol = h * 32 + lane;      // float2 column in the full row

    float2 acc = make_float2(0.f, 0.f);

    // 50 gathers per warp in ascending-id order; unroll 5 = measured
    // optimum; .cg = no L1 allocation (no L1 reuse on the gather stream).
    #pragma unroll 5
    for (int t = s; t < CV_SEQ; t += 4) {
        const float2 v = __ldcg(&W2[s_ids[t] * CV_D2 + dcol]);
        acc.x += v.x; acc.y += v.y;
    }

    s_acc[s][dcol] = acc;                // streams write disjoint [s][dcol]
    __syncthreads();

    // Threads 0..63: fold the 4 stream partials, add bias, store 512B row.
    if (tid < CV_D2) {
        float2 a = s_acc[0][tid];
        #pragma unroll
        for (int g = 1; g < 4; g++) {
            const float2 v = s_acc[g][tid];
            a.x += v.x; a.y += v.y;
        }
        const float2 bb = __ldg(&bias2[tid]);
        a.x += bb.x; a.y += bb.y;
        out2[b * CV_D2 + tid] = a;
    }
}

extern "C" void kernel_launch(void* const* d_in, const int* in_sizes, int n_in,
                              void* d_out, int out_size)
{
    const int*   token_ids = (const int*)d_in[0];      // [1024, 200] int32
    const float* W         = (const float*)d_in[1];    // [100000, 128] f32
    const float* bias      = (const float*)d_in[2];    // [128] f32
    float*       out       = (float*)d_out;            // [1024, 128] f32

    (void)in_sizes; (void)n_in; (void)out_size;

    count_vectorizer_kernel<<<CV_BATCH, 256>>>(
        token_ids,
        reinterpret_cast<const float2*>(W),
        reinterpret_cast<const float2*>(bias),
        reinterpret_cast<float2*>(out));
}